// round 2
// baseline (speedup 1.0000x reference)
#include <cuda_runtime.h>

// Problem constants (fixed by the reference: x shape (4,40,64,66,64) f32)
#define B_     4
#define C_IN   40
#define D_     64
#define H_IN   66
#define W_     64
#define HP_    17          // (66 + pad_1)/4, pad_1 = 2
#define C_OUT  160         // C_IN * PIXEL
#define W4_    16          // W_/4 float4 per row
#define TOTAL_OUT  (B_ * C_OUT * D_ * HP_ * W_)   // 44,564,480 floats
#define TOTAL4     (TOTAL_OUT / 4)                // 11,141,120 float4

// out[b, c_out, d, hp, w] = x[b, c_out>>2, d + 2 - j, h, w]
//   j = (c_out % 40) >> 3                      (D-shift group)
//   h = hp*4 + (c_out & 3), wrap -66 if >= 66  (circular H pad)
//   zero if (d + 2 - j) outside [0, 64)
__global__ void torch_shift_kernel(const float4* __restrict__ x,
                                   float4* __restrict__ out) {
    unsigned idx = blockIdx.x * blockDim.x + threadIdx.x;
    if (idx >= TOTAL4) return;

    unsigned w4 = idx & (W4_ - 1);
    unsigned t  = idx >> 4;            // / W4_
    unsigned hp = t % HP_;  t /= HP_;  // fast unsigned div-by-const (IMAD.HI)
    unsigned d  = t & (D_ - 1); t >>= 6;
    unsigned c_out = t % C_OUT;
    unsigned b     = t / C_OUT;

    unsigned j = (c_out % 40) >> 3;
    int src_d = (int)d + 2 - (int)j;

    float4 v;
    if ((unsigned)src_d < (unsigned)D_) {
        unsigned c = c_out >> 2;
        unsigned p = c_out & 3;
        unsigned h = hp * 4 + p;
        if (h >= H_IN) h -= H_IN;      // circular wrap (only h=66,67)
        unsigned in_idx = (((b * C_IN + c) * D_ + (unsigned)src_d) * H_IN + h) * W4_ + w4;
        v = __ldg(&x[in_idx]);
    } else {
        v = make_float4(0.f, 0.f, 0.f, 0.f);
    }
    out[idx] = v;
}

// Trailing scalar(s): pad_1 = 2, emitted as float (harness flattens the
// (out, pad_1) tuple into one float32 buffer).
__global__ void tail_kernel(float* __restrict__ out, int start, int n) {
    int i = start + blockIdx.x * blockDim.x + threadIdx.x;
    if (i < n) out[i] = 2.0f;
}

extern "C" void kernel_launch(void* const* d_in, const int* in_sizes, int n_in,
                              void* d_out, int out_size) {
    const float4* x = (const float4*)d_in[0];
    float4* out4 = (float4*)d_out;

    const int threads = 256;
    const int blocks = (TOTAL4 + threads - 1) / threads;
    torch_shift_kernel<<<blocks, threads>>>(x, out4);

    int tail = out_size - TOTAL_OUT;
    if (tail > 0) {
        int tb = (tail + 31) / 32;
        tail_kernel<<<tb, 32>>>((float*)d_out, TOTAL_OUT, out_size);
    }
}

// round 4
// speedup vs baseline: 1.0026x; 1.0026x over previous
#include <cuda_runtime.h>

// Problem constants (fixed by the reference: x shape (4,40,64,66,64) f32)
#define B_     4
#define C_IN   40
#define D_     64
#define H_IN   66
#define W_     64
#define HP_    17          // (66 + pad_1)/4, pad_1 = 2
#define C_OUT  160         // C_IN * PIXEL
#define W4_    16          // W_/4 float4 per row
#define TOTAL_OUT  (B_ * C_OUT * D_ * HP_ * W_)   // 44,564,480 floats
#define TOTAL4     (TOTAL_OUT / 4)                // 11,141,120 float4

// out[b, c_out, d, hp, w] = x[b, c_out>>2, d + 2 - j, h, w]
//   j = (c_out % 40) >> 3                      (D-shift group)
//   h = hp*4 + (c_out & 3), wrap -66 if >= 66  (circular H pad)
//   zero if (d + 2 - j) outside [0, 64)
// Thread 0 additionally writes the trailing pad_1 scalar(s) = 2.0f,
// eliminating the separate 3.7us tail launch measured in R2.
// (R3 was an infra failure; this is the R2 candidate re-benched.)
__global__ void torch_shift_kernel(const float4* __restrict__ x,
                                   float4* __restrict__ out,
                                   int tail_start, int out_size) {
    unsigned idx = blockIdx.x * blockDim.x + threadIdx.x;

    if (idx == 0) {
        float* of = (float*)out;
        for (int i = tail_start; i < out_size; i++) of[i] = 2.0f;
    }

    if (idx >= TOTAL4) return;

    unsigned w4 = idx & (W4_ - 1);
    unsigned t  = idx >> 4;            // / W4_
    unsigned hp = t % HP_;  t /= HP_;  // fast unsigned div-by-const
    unsigned d  = t & (D_ - 1); t >>= 6;
    unsigned c_out = t % C_OUT;
    unsigned b     = t / C_OUT;

    unsigned j = (c_out % 40) >> 3;
    int src_d = (int)d + 2 - (int)j;

    float4 v;
    if ((unsigned)src_d < (unsigned)D_) {
        unsigned c = c_out >> 2;
        unsigned p = c_out & 3;
        unsigned h = hp * 4 + p;
        if (h >= H_IN) h -= H_IN;      // circular wrap (only h=66,67)
        unsigned in_idx = (((b * C_IN + c) * D_ + (unsigned)src_d) * H_IN + h) * W4_ + w4;
        v = __ldcs(&x[in_idx]);        // read-once: evict-first
    } else {
        v = make_float4(0.f, 0.f, 0.f, 0.f);
    }
    __stcs(&out[idx], v);              // write-once streaming store
}

extern "C" void kernel_launch(void* const* d_in, const int* in_sizes, int n_in,
                              void* d_out, int out_size) {
    const float4* x = (const float4*)d_in[0];
    float4* out4 = (float4*)d_out;

    const int threads = 256;
    const int blocks = (TOTAL4 + threads - 1) / threads;
    torch_shift_kernel<<<blocks, threads>>>(x, out4, TOTAL_OUT, out_size);
}